// round 3
// baseline (speedup 1.0000x reference)
#include <cuda_runtime.h>
#include <math.h>

#define EPSV 0.001
#define KMIX 8
#define TAB_N 4096
#define XMIN -6.0
#define XMAX 6.0

// (f_i, f_{i+1}-f_i) per interval
__device__ float2 g_tab[TAB_N];

// ---------- exact f(x) in double precision (setup only) ----------
__device__ double acn_f_eval(double x, const double* m, const double* v,
                             const double* pr) {
    double denom = 0.0;
    for (int k = 0; k < KMIX; k++) {
        double t = (x - m[k]) / v[k];
        denom += pr[k] * exp(-0.5 * t * t);
    }
    double out = 0.0;
    for (int k = 0; k < KMIX; k++) {
        double ve = v[k] + EPSV;
        double t = (x - m[k]) / ve;
        double pxk = pr[k] * exp(-0.5 * t * t);
        double tau = pxk / (denom + EPSV);
        double hat = (x - m[k]) / sqrt(ve);
        out += tau / sqrt(pr[k] + EPSV) * hat;
    }
    return out;
}

__global__ void acn_table_kernel(const float* __restrict__ mean,
                                 const float* __restrict__ variance,
                                 const float* __restrict__ prior) {
    int i = blockIdx.x * blockDim.x + threadIdx.x;
    if (i >= TAB_N) return;

    double m[KMIX], v[KMIX], p[KMIX];
    double pmax = -1e30;
    for (int k = 0; k < KMIX; k++) {
        double raw = (double)variance[k];
        v[k] = log1p(exp(raw));             // softplus
        m[k] = (double)mean[k];
        p[k] = (double)prior[k];
        pmax = fmax(pmax, p[k]);
    }
    double psum = 0.0;
    for (int k = 0; k < KMIX; k++) { p[k] = exp(p[k] - pmax); psum += p[k]; }
    for (int k = 0; k < KMIX; k++) p[k] /= psum;

    const double h = (XMAX - XMIN) / (double)TAB_N;
    double x0 = XMIN + (double)i * h;
    double f0 = acn_f_eval(x0, m, v, p);
    double f1 = acn_f_eval(x0 + h, m, v, p);
    g_tab[i] = make_float2((float)f0, (float)(f1 - f0));
}

// ---------- main streaming kernel: LUT + lerp ----------
__global__ void __launch_bounds__(256)
acn_lut_kernel(const float4* __restrict__ x4, float4* __restrict__ o4, int n4,
               const float* __restrict__ x_tail, float* __restrict__ o_tail,
               int ntail) {
    __shared__ float2 tab[TAB_N];   // 32 KB

    // cooperative table copy (g_tab is L2-resident after first block)
    {
        float4* ts = (float4*)tab;
        const float4* tg = (const float4*)g_tab;
#pragma unroll
        for (int i = threadIdx.x; i < TAB_N / 2; i += 256) ts[i] = tg[i];
    }
    __syncthreads();

    const float invh = (float)((double)TAB_N / (XMAX - XMIN));
    const float offs = (float)(-(XMIN) * ((double)TAB_N / (XMAX - XMIN)));
    const float umax = (float)TAB_N - 0.5f;   // clamp inside last interval

    const int stride = gridDim.x * blockDim.x;
    for (int i = blockIdx.x * blockDim.x + threadIdx.x; i < n4; i += stride) {
        float4 xv = x4[i];
        float4 ov;

        float u0 = fminf(fmaxf(fmaf(xv.x, invh, offs), 0.f), umax);
        float u1 = fminf(fmaxf(fmaf(xv.y, invh, offs), 0.f), umax);
        float u2 = fminf(fmaxf(fmaf(xv.z, invh, offs), 0.f), umax);
        float u3 = fminf(fmaxf(fmaf(xv.w, invh, offs), 0.f), umax);

        int i0 = (int)u0, i1 = (int)u1, i2 = (int)u2, i3 = (int)u3;
        float fr0 = u0 - (float)i0;
        float fr1 = u1 - (float)i1;
        float fr2 = u2 - (float)i2;
        float fr3 = u3 - (float)i3;

        float2 e0 = tab[i0];
        float2 e1 = tab[i1];
        float2 e2 = tab[i2];
        float2 e3 = tab[i3];

        ov.x = fmaf(fr0, e0.y, e0.x);
        ov.y = fmaf(fr1, e1.y, e1.x);
        ov.z = fmaf(fr2, e2.y, e2.x);
        ov.w = fmaf(fr3, e3.y, e3.x);

        o4[i] = ov;
    }

    // scalar tail (dead for this shape; kept for safety)
    if (blockIdx.x == 0 && (int)threadIdx.x < ntail) {
        int idx = (int)threadIdx.x;
        float u = fminf(fmaxf(fmaf(x_tail[idx], invh, offs), 0.f), umax);
        int ii = (int)u;
        float fr = u - (float)ii;
        float2 e = tab[ii];
        o_tail[idx] = fmaf(fr, e.y, e.x);
    }
}

extern "C" void kernel_launch(void* const* d_in, const int* in_sizes, int n_in,
                              void* d_out, int out_size) {
    const float* x        = (const float*)d_in[0];
    const float* mean     = (const float*)d_in[1];
    const float* variance = (const float*)d_in[2];
    const float* prior    = (const float*)d_in[3];
    float* out = (float*)d_out;

    int n     = in_sizes[0];
    int n4    = n >> 2;
    int ntail = n & 3;

    acn_table_kernel<<<TAB_N / 256, 256>>>(mean, variance, prior);

    // 7 blocks/SM (32KB smem each, 228KB carveout) * 148 SMs = one full wave
    acn_lut_kernel<<<1036, 256>>>(
        (const float4*)x, (float4*)out, n4,
        x + (n - ntail), out + (n - ntail), ntail);
}

// round 4
// speedup vs baseline: 1.7773x; 1.7773x over previous
#include <cuda_runtime.h>
#include <math.h>

#define EPSV 0.001
#define KMIX 8
#define TAB_N 2048
#define XMIN -6.0
#define XMAX 6.0

// raw f values at TAB_N+1 grid points
__device__ float g_f[TAB_N + 1];

// ---------- table build: one point per thread, float math ----------
__global__ void acn_table_kernel(const float* __restrict__ mean,
                                 const float* __restrict__ variance,
                                 const float* __restrict__ prior) {
    int i = blockIdx.x * blockDim.x + threadIdx.x;
    if (i > TAB_N) return;

    // scalar parameter prep in double (16 transcendentals, cheap)
    double m[KMIX], v[KMIX], p[KMIX];
    double pmax = -1e30;
    for (int k = 0; k < KMIX; k++) {
        v[k] = log1p(exp((double)variance[k]));   // softplus
        m[k] = (double)mean[k];
        p[k] = (double)prior[k];
        pmax = fmax(pmax, p[k]);
    }
    double psum = 0.0;
    for (int k = 0; k < KMIX; k++) { p[k] = exp(p[k] - pmax); psum += p[k]; }

    // fold to float coefficients
    float fm[KMIX], fa[KMIX], fb[KMIX], fp[KMIX], fw[KMIX];
    for (int k = 0; k < KMIX; k++) {
        double pr = p[k] / psum;
        double ve = v[k] + EPSV;
        fm[k] = (float)m[k];
        fa[k] = (float)(-0.5 / (v[k] * v[k]));    // denom exponent (base e)
        fb[k] = (float)(-0.5 / (ve * ve));        // numer exponent (base e)
        fp[k] = (float)pr;
        fw[k] = (float)(pr / (sqrt(pr + EPSV) * sqrt(ve)));
    }

    const float h = (float)((XMAX - XMIN) / (double)TAB_N);
    float x = (float)XMIN + (float)i * h;

    float denom = 0.f, num = 0.f;
#pragma unroll
    for (int k = 0; k < KMIX; k++) {
        float d  = x - fm[k];
        float dd = d * d;
        denom = fmaf(fp[k], __expf(fa[k] * dd), denom);
        num   = fmaf(fw[k] * d, __expf(fb[k] * dd), num);
    }
    g_f[i] = num / (denom + (float)EPSV);
}

// ---------- main streaming kernel: LUT + lerp, 2-wide ILP ----------
__global__ void __launch_bounds__(256)
acn_lut_kernel(const float4* __restrict__ x4, float4* __restrict__ o4, int n4,
               const float* __restrict__ x_tail, float* __restrict__ o_tail,
               int ntail) {
    __shared__ float2 tab[TAB_N];   // 16 KB: (f_i, f_{i+1}-f_i)

    for (int i = threadIdx.x; i < TAB_N; i += 256) {
        float f0 = g_f[i];
        float f1 = g_f[i + 1];
        tab[i] = make_float2(f0, f1 - f0);
    }
    __syncthreads();

    const float invh = (float)((double)TAB_N / (XMAX - XMIN));
    const float offs = (float)(-(XMIN) * ((double)TAB_N / (XMAX - XMIN)));
    const float umax = (float)TAB_N - 0.5f;

    const int npairs = n4 >> 1;            // n4 is even for this shape
    const int stride = gridDim.x * blockDim.x;
    for (int i = blockIdx.x * blockDim.x + threadIdx.x; i < npairs; i += stride) {
        float4 xa = x4[2 * i];
        float4 xb = x4[2 * i + 1];

        float u0 = fminf(fmaxf(fmaf(xa.x, invh, offs), 0.f), umax);
        float u1 = fminf(fmaxf(fmaf(xa.y, invh, offs), 0.f), umax);
        float u2 = fminf(fmaxf(fmaf(xa.z, invh, offs), 0.f), umax);
        float u3 = fminf(fmaxf(fmaf(xa.w, invh, offs), 0.f), umax);
        float u4 = fminf(fmaxf(fmaf(xb.x, invh, offs), 0.f), umax);
        float u5 = fminf(fmaxf(fmaf(xb.y, invh, offs), 0.f), umax);
        float u6 = fminf(fmaxf(fmaf(xb.z, invh, offs), 0.f), umax);
        float u7 = fminf(fmaxf(fmaf(xb.w, invh, offs), 0.f), umax);

        int i0 = (int)u0, i1 = (int)u1, i2 = (int)u2, i3 = (int)u3;
        int i4 = (int)u4, i5 = (int)u5, i6 = (int)u6, i7 = (int)u7;

        float2 e0 = tab[i0];
        float2 e1 = tab[i1];
        float2 e2 = tab[i2];
        float2 e3 = tab[i3];
        float2 e4 = tab[i4];
        float2 e5 = tab[i5];
        float2 e6 = tab[i6];
        float2 e7 = tab[i7];

        float4 oa, ob;
        oa.x = fmaf(u0 - (float)i0, e0.y, e0.x);
        oa.y = fmaf(u1 - (float)i1, e1.y, e1.x);
        oa.z = fmaf(u2 - (float)i2, e2.y, e2.x);
        oa.w = fmaf(u3 - (float)i3, e3.y, e3.x);
        ob.x = fmaf(u4 - (float)i4, e4.y, e4.x);
        ob.y = fmaf(u5 - (float)i5, e5.y, e5.x);
        ob.z = fmaf(u6 - (float)i6, e6.y, e6.x);
        ob.w = fmaf(u7 - (float)i7, e7.y, e7.x);

        o4[2 * i]     = oa;
        o4[2 * i + 1] = ob;
    }

    // odd-float4 remainder (dead for this shape)
    if ((n4 & 1) && blockIdx.x == 0 && threadIdx.x == 0) {
        int i = n4 - 1;
        float4 xv = x4[i];
        float4 ov;
        float us[4] = {xv.x, xv.y, xv.z, xv.w};
        float* ovp = &ov.x;
        for (int j = 0; j < 4; j++) {
            float u = fminf(fmaxf(fmaf(us[j], invh, offs), 0.f), umax);
            int ii = (int)u;
            float2 e = tab[ii];
            ovp[j] = fmaf(u - (float)ii, e.y, e.x);
        }
        o4[i] = ov;
    }

    // scalar tail (dead for this shape)
    if (blockIdx.x == 0 && (int)threadIdx.x < ntail) {
        int idx = (int)threadIdx.x;
        float u = fminf(fmaxf(fmaf(x_tail[idx], invh, offs), 0.f), umax);
        int ii = (int)u;
        float2 e = tab[ii];
        o_tail[idx] = fmaf(u - (float)ii, e.y, e.x);
    }
}

extern "C" void kernel_launch(void* const* d_in, const int* in_sizes, int n_in,
                              void* d_out, int out_size) {
    const float* x        = (const float*)d_in[0];
    const float* mean     = (const float*)d_in[1];
    const float* variance = (const float*)d_in[2];
    const float* prior    = (const float*)d_in[3];
    float* out = (float*)d_out;

    int n     = in_sizes[0];
    int n4    = n >> 2;
    int ntail = n & 3;

    acn_table_kernel<<<(TAB_N + 256) / 256, 256>>>(mean, variance, prior);

    acn_lut_kernel<<<2048, 256>>>(
        (const float4*)x, (float4*)out, n4,
        x + (n - ntail), out + (n - ntail), ntail);
}

// round 5
// speedup vs baseline: 4.1769x; 2.3501x over previous
#include <cuda_runtime.h>
#include <math.h>

#define EPSV 0.001f
#define KMIX 8
#define TAB_N 2048
#define XMINF -6.0f
#define XMAXF 6.0f

// raw f values at TAB_N+1 grid points
__device__ float g_f[TAB_N + 1];

// ---------- table build: one point per thread, ALL-float math ----------
__global__ void acn_table_kernel(const float* __restrict__ mean,
                                 const float* __restrict__ variance,
                                 const float* __restrict__ prior) {
    int i = blockIdx.x * blockDim.x + threadIdx.x;
    if (i > TAB_N) return;

    // scalar parameter prep in float (fast MUFU transcendentals)
    float m[KMIX], v[KMIX], p[KMIX];
    float pmax = -1e30f;
#pragma unroll
    for (int k = 0; k < KMIX; k++) {
        v[k] = log1pf(expf(variance[k]));   // softplus (variance in [1e-3,1e-2])
        m[k] = mean[k];
        p[k] = prior[k];
        pmax = fmaxf(pmax, p[k]);
    }
    float psum = 0.f;
#pragma unroll
    for (int k = 0; k < KMIX; k++) { p[k] = expf(p[k] - pmax); psum += p[k]; }
    float pinv = 1.f / psum;

    float fa[KMIX], fb[KMIX], fp[KMIX], fw[KMIX];
#pragma unroll
    for (int k = 0; k < KMIX; k++) {
        float pr = p[k] * pinv;
        float ve = v[k] + EPSV;
        fa[k] = -0.5f / (v[k] * v[k]);      // denom exponent (base e)
        fb[k] = -0.5f / (ve * ve);          // numer exponent (base e)
        fp[k] = pr;
        fw[k] = pr / (sqrtf(pr + EPSV) * sqrtf(ve));
    }

    const float h = (XMAXF - XMINF) / (float)TAB_N;
    float x = XMINF + (float)i * h;

    float denom = 0.f, num = 0.f;
#pragma unroll
    for (int k = 0; k < KMIX; k++) {
        float d  = x - m[k];
        float dd = d * d;
        denom = fmaf(fp[k], __expf(fa[k] * dd), denom);
        num   = fmaf(fw[k] * d, __expf(fb[k] * dd), num);
    }
    g_f[i] = num / (denom + EPSV);
}

// ---------- main streaming kernel: LUT + lerp, 4-wide ILP ----------
__global__ void __launch_bounds__(256)
acn_lut_kernel(const float4* __restrict__ x4, float4* __restrict__ o4, int n4,
               const float* __restrict__ x_tail, float* __restrict__ o_tail,
               int ntail) {
    __shared__ float2 tab[TAB_N];   // 16 KB: (f_i, f_{i+1}-f_i)

    for (int i = threadIdx.x; i < TAB_N; i += 256) {
        float f0 = g_f[i];
        float f1 = g_f[i + 1];
        tab[i] = make_float2(f0, f1 - f0);
    }
    __syncthreads();

    const float invh = (float)TAB_N / (XMAXF - XMINF);
    const float offs = -XMINF * ((float)TAB_N / (XMAXF - XMINF));
    const float umax = (float)TAB_N - 0.5f;

    const int nquad  = n4 >> 2;            // groups of 4 float4 (16 elems)
    const int stride = gridDim.x * blockDim.x;

    for (int q = blockIdx.x * blockDim.x + threadIdx.x; q < nquad; q += stride) {
        int base = q << 2;
        float4 xv[4];
        xv[0] = x4[base + 0];
        xv[1] = x4[base + 1];
        xv[2] = x4[base + 2];
        xv[3] = x4[base + 3];

        float4 ov[4];
#pragma unroll
        for (int a = 0; a < 4; a++) {
            float u0 = fminf(fmaxf(fmaf(xv[a].x, invh, offs), 0.f), umax);
            float u1 = fminf(fmaxf(fmaf(xv[a].y, invh, offs), 0.f), umax);
            float u2 = fminf(fmaxf(fmaf(xv[a].z, invh, offs), 0.f), umax);
            float u3 = fminf(fmaxf(fmaf(xv[a].w, invh, offs), 0.f), umax);

            int i0 = (int)u0, i1 = (int)u1, i2 = (int)u2, i3 = (int)u3;

            float2 e0 = tab[i0];
            float2 e1 = tab[i1];
            float2 e2 = tab[i2];
            float2 e3 = tab[i3];

            ov[a].x = fmaf(u0 - (float)i0, e0.y, e0.x);
            ov[a].y = fmaf(u1 - (float)i1, e1.y, e1.x);
            ov[a].z = fmaf(u2 - (float)i2, e2.y, e2.x);
            ov[a].w = fmaf(u3 - (float)i3, e3.y, e3.x);
        }

        o4[base + 0] = ov[0];
        o4[base + 1] = ov[1];
        o4[base + 2] = ov[2];
        o4[base + 3] = ov[3];
    }

    // float4 remainder (n4 % 4) — dead for this shape, kept for safety
    int rem = n4 & 3;
    if (blockIdx.x == 0 && (int)threadIdx.x < rem) {
        int i = (nquad << 2) + (int)threadIdx.x;
        float4 xv = x4[i];
        float4 ov;
        float xs[4] = {xv.x, xv.y, xv.z, xv.w};
        float* op = &ov.x;
#pragma unroll
        for (int j = 0; j < 4; j++) {
            float u = fminf(fmaxf(fmaf(xs[j], invh, offs), 0.f), umax);
            int ii = (int)u;
            float2 e = tab[ii];
            op[j] = fmaf(u - (float)ii, e.y, e.x);
        }
        o4[i] = ov;
    }

    // scalar tail — dead for this shape
    if (blockIdx.x == 0 && (int)threadIdx.x < ntail) {
        int idx = (int)threadIdx.x;
        float u = fminf(fmaxf(fmaf(x_tail[idx], invh, offs), 0.f), umax);
        int ii = (int)u;
        float2 e = tab[ii];
        o_tail[idx] = fmaf(u - (float)ii, e.y, e.x);
    }
}

extern "C" void kernel_launch(void* const* d_in, const int* in_sizes, int n_in,
                              void* d_out, int out_size) {
    const float* x        = (const float*)d_in[0];
    const float* mean     = (const float*)d_in[1];
    const float* variance = (const float*)d_in[2];
    const float* prior    = (const float*)d_in[3];
    float* out = (float*)d_out;

    int n     = in_sizes[0];
    int n4    = n >> 2;
    int ntail = n & 3;

    acn_table_kernel<<<(TAB_N + 256) / 256, 256>>>(mean, variance, prior);

    acn_lut_kernel<<<2048, 256>>>(
        (const float4*)x, (float4*)out, n4,
        x + (n - ntail), out + (n - ntail), ntail);
}

// round 6
// speedup vs baseline: 5.2326x; 1.2527x over previous
#include <cuda_runtime.h>
#include <math.h>

#define EPSV 0.001f
#define KMIX 8
#define TAB_N 2048
#define XMINF -6.0f
#define XMAXF 6.0f

// raw f values at TAB_N+1 grid points
__device__ float g_f[TAB_N + 1];

// ---------- table build: one point per thread, ALL-float math ----------
__global__ void acn_table_kernel(const float* __restrict__ mean,
                                 const float* __restrict__ variance,
                                 const float* __restrict__ prior) {
    int i = blockIdx.x * blockDim.x + threadIdx.x;
    if (i > TAB_N) return;

    float m[KMIX], v[KMIX], p[KMIX];
    float pmax = -1e30f;
#pragma unroll
    for (int k = 0; k < KMIX; k++) {
        v[k] = log1pf(expf(variance[k]));   // softplus
        m[k] = mean[k];
        p[k] = prior[k];
        pmax = fmaxf(pmax, p[k]);
    }
    float psum = 0.f;
#pragma unroll
    for (int k = 0; k < KMIX; k++) { p[k] = expf(p[k] - pmax); psum += p[k]; }
    float pinv = 1.f / psum;

    float fa[KMIX], fb[KMIX], fp[KMIX], fw[KMIX];
#pragma unroll
    for (int k = 0; k < KMIX; k++) {
        float pr = p[k] * pinv;
        float ve = v[k] + EPSV;
        fa[k] = -0.5f / (v[k] * v[k]);
        fb[k] = -0.5f / (ve * ve);
        fp[k] = pr;
        fw[k] = pr / (sqrtf(pr + EPSV) * sqrtf(ve));
    }

    const float h = (XMAXF - XMINF) / (float)TAB_N;
    float x = XMINF + (float)i * h;

    float denom = 0.f, num = 0.f;
#pragma unroll
    for (int k = 0; k < KMIX; k++) {
        float d  = x - m[k];
        float dd = d * d;
        denom = fmaf(fp[k], __expf(fa[k] * dd), denom);
        num   = fmaf(fw[k] * d, __expf(fb[k] * dd), num);
    }
    g_f[i] = num / (denom + EPSV);
}

// ---------- main streaming kernel: LUT + lerp, 2-wide ILP (R4 config) ----------
__global__ void __launch_bounds__(256)
acn_lut_kernel(const float4* __restrict__ x4, float4* __restrict__ o4, int n4,
               const float* __restrict__ x_tail, float* __restrict__ o_tail,
               int ntail) {
    __shared__ float2 tab[TAB_N];   // 16 KB: (f_i, f_{i+1}-f_i)

    for (int i = threadIdx.x; i < TAB_N; i += 256) {
        float f0 = g_f[i];
        float f1 = g_f[i + 1];
        tab[i] = make_float2(f0, f1 - f0);
    }
    __syncthreads();

    const float invh = (float)TAB_N / (XMAXF - XMINF);
    const float offs = -XMINF * ((float)TAB_N / (XMAXF - XMINF));
    const float umax = (float)TAB_N - 0.5f;

    const int npairs = n4 >> 1;            // n4 is even for this shape
    const int stride = gridDim.x * blockDim.x;
    for (int i = blockIdx.x * blockDim.x + threadIdx.x; i < npairs; i += stride) {
        float4 xa = x4[2 * i];
        float4 xb = x4[2 * i + 1];

        float u0 = fminf(fmaxf(fmaf(xa.x, invh, offs), 0.f), umax);
        float u1 = fminf(fmaxf(fmaf(xa.y, invh, offs), 0.f), umax);
        float u2 = fminf(fmaxf(fmaf(xa.z, invh, offs), 0.f), umax);
        float u3 = fminf(fmaxf(fmaf(xa.w, invh, offs), 0.f), umax);
        float u4 = fminf(fmaxf(fmaf(xb.x, invh, offs), 0.f), umax);
        float u5 = fminf(fmaxf(fmaf(xb.y, invh, offs), 0.f), umax);
        float u6 = fminf(fmaxf(fmaf(xb.z, invh, offs), 0.f), umax);
        float u7 = fminf(fmaxf(fmaf(xb.w, invh, offs), 0.f), umax);

        int i0 = (int)u0, i1 = (int)u1, i2 = (int)u2, i3 = (int)u3;
        int i4 = (int)u4, i5 = (int)u5, i6 = (int)u6, i7 = (int)u7;

        float2 e0 = tab[i0];
        float2 e1 = tab[i1];
        float2 e2 = tab[i2];
        float2 e3 = tab[i3];
        float2 e4 = tab[i4];
        float2 e5 = tab[i5];
        float2 e6 = tab[i6];
        float2 e7 = tab[i7];

        float4 oa, ob;
        oa.x = fmaf(u0 - (float)i0, e0.y, e0.x);
        oa.y = fmaf(u1 - (float)i1, e1.y, e1.x);
        oa.z = fmaf(u2 - (float)i2, e2.y, e2.x);
        oa.w = fmaf(u3 - (float)i3, e3.y, e3.x);
        ob.x = fmaf(u4 - (float)i4, e4.y, e4.x);
        ob.y = fmaf(u5 - (float)i5, e5.y, e5.x);
        ob.z = fmaf(u6 - (float)i6, e6.y, e6.x);
        ob.w = fmaf(u7 - (float)i7, e7.y, e7.x);

        o4[2 * i]     = oa;
        o4[2 * i + 1] = ob;
    }

    // odd-float4 remainder (dead for this shape)
    if ((n4 & 1) && blockIdx.x == 0 && threadIdx.x == 0) {
        int i = n4 - 1;
        float4 xv = x4[i];
        float4 ov;
        float xs[4] = {xv.x, xv.y, xv.z, xv.w};
        float* op = &ov.x;
        for (int j = 0; j < 4; j++) {
            float u = fminf(fmaxf(fmaf(xs[j], invh, offs), 0.f), umax);
            int ii = (int)u;
            float2 e = tab[ii];
            op[j] = fmaf(u - (float)ii, e.y, e.x);
        }
        o4[i] = ov;
    }

    // scalar tail (dead for this shape)
    if (blockIdx.x == 0 && (int)threadIdx.x < ntail) {
        int idx = (int)threadIdx.x;
        float u = fminf(fmaxf(fmaf(x_tail[idx], invh, offs), 0.f), umax);
        int ii = (int)u;
        float2 e = tab[ii];
        o_tail[idx] = fmaf(u - (float)ii, e.y, e.x);
    }
}

extern "C" void kernel_launch(void* const* d_in, const int* in_sizes, int n_in,
                              void* d_out, int out_size) {
    const float* x        = (const float*)d_in[0];
    const float* mean     = (const float*)d_in[1];
    const float* variance = (const float*)d_in[2];
    const float* prior    = (const float*)d_in[3];
    float* out = (float*)d_out;

    int n     = in_sizes[0];
    int n4    = n >> 2;
    int ntail = n & 3;

    acn_table_kernel<<<(TAB_N + 256) / 256, 256>>>(mean, variance, prior);

    acn_lut_kernel<<<2048, 256>>>(
        (const float4*)x, (float4*)out, n4,
        x + (n - ntail), out + (n - ntail), ntail);
}